// round 4
// baseline (speedup 1.0000x reference)
#include <cuda_runtime.h>
#include <cuda_bf16.h>

#define PP 16
#define NN 128
#define II 256
#define OO 256
#define KE 4096          // GEMM inner dim = I*P
#define TRI(p,q) ((p)*((p)+1)/2 + (q))
#define STRIDE 372       // general-path blob stride

typedef unsigned long long u64;

// ---------------- scratch (static __device__, allocation-free) --------------
__device__ int   g_fast;
__device__ float g_z[16], g_zz[16], g_Qi[256], g_sc[4]; // sc: l2, A, t4
__device__ float g_Et[KE * NN];          // 2 MB  : f[k][n], k = i*16+p (c2-scaled Qi e)
__device__ float g_part[16 * NN * OO];   // 2 MB  : split-K partials
__device__ float g_vp[II * NN];          // varpart[i][n]
// general-path scratch
__device__ float g_blob[(size_t)II * OO * STRIDE];
__device__ float g_xmT[II * NN];
__device__ float g_xvT[II * NN];

__device__ __forceinline__ float ex2(float x) {
    float y; asm("ex2.approx.ftz.f32 %0, %1;" : "=f"(y) : "f"(x)); return y;
}
__device__ __forceinline__ u64 pk2(float lo, float hi) {
    u64 r; asm("mov.b64 %0, {%1,%2};" : "=l"(r) : "f"(lo), "f"(hi)); return r;
}
__device__ __forceinline__ void upk2(float& lo, float& hi, u64 v) {
    asm("mov.b64 {%0,%1}, %2;" : "=f"(lo), "=f"(hi) : "l"(v));
}
__device__ __forceinline__ u64 ffma2(u64 a, u64 b, u64 c) {
    u64 r; asm("fma.rn.f32x2 %0, %1, %2, %3;" : "=l"(r) : "l"(a), "l"(b), "l"(c)); return r;
}
__device__ __forceinline__ u64 fmul2(u64 a, u64 b) {
    u64 r; asm("mul.rn.f32x2 %0, %1, %2;" : "=l"(r) : "l"(a), "l"(b)); return r;
}

#define KLOG (-0.72134752044448170f)   // -log2(e)/2
#define C2G  ( 0.39894228040143270f)   // 1/sqrt(2pi)
#define SQ2PI 2.5066282746310002f

// ============ setup: g_fast=1 + shared 16x16 factorization ==================
__global__ void k_setup(const float* __restrict__ zp, const float* __restrict__ lp,
                        const float* __restrict__ sp, const float* __restrict__ jp)
{
    __shared__ float L[16][16], M[16][16], invd[16], z[16], sc[8];
    int t = threadIdx.x;   // 32 threads
    if (t == 0) g_fast = 1;
    if (t < 16) z[t] = tanhf(zp[t]);
    if (t == 0) {
        float l   = __expf(lp[0]) + 0.2f;
        float s   = __expf(sp[0]) + 0.1f;
        float jit = __expf(jp[0]) + 0.01f;
        float l2  = l * l;
        sc[0] = l2;
        sc[1] = s * s * l;            // A
        sc[2] = SQ2PI * s * s * l;    // t4
        sc[3] = __fdividef(1.0f, l * SQ2PI);              // coef
        sc[4] = -__fdividef(0.72134752044448170f, l2);    // c1z (log2 domain)
        sc[5] = jit * jit * sc[3] * __fdividef(1.0f, s * s); // noise
    }
    __syncwarp();
    if (t < 16) {
        for (int q = 0; q <= t; q++) {
            float d = z[t] - z[q];
            float v = sc[3] * ex2(sc[4] * d * d);
            if (q == t) v += sc[5];
            L[t][q] = v;
        }
    }
    __syncwarp();
    // Cholesky
    for (int k = 0; k < 16; k++) {
        if (t == k) { float rs = rsqrtf(L[k][k]); invd[k] = rs; L[k][k] *= rs; }
        __syncwarp();
        if (t < 16 && t > k) L[t][k] *= invd[k];
        __syncwarp();
        if (t < 16 && t > k)
            for (int q = k + 1; q <= t; q++) L[t][q] -= L[t][k] * L[q][k];
        __syncwarp();
    }
    // Linv column t
    if (t < 16) {
        for (int p = 0; p < t; p++) M[p][t] = 0.0f;
        M[t][t] = invd[t];
        for (int p = t + 1; p < 16; p++) {
            float acc = 0.0f;
            for (int r = t; r < p; r++) acc += L[p][r] * M[r][t];
            M[p][t] = -acc * invd[p];
        }
    }
    __syncwarp();
    // Qinv row t
    if (t < 16) {
        for (int b = 0; b < 16; b++) {
            float s = 0.0f;
            for (int p = 0; p < 16; p++) s += M[p][t] * M[p][b];
            g_Qi[t * 16 + b] = s;
        }
        g_z[t]  = z[t];
        g_zz[t] = z[t] * z[t];
        if (t < 3) g_sc[t] = sc[t];
    }
}

// ============================ uniformity check ==============================
__global__ void __launch_bounds__(256) k_check(
    const float* __restrict__ zp, const float* __restrict__ lp,
    const float* __restrict__ sp, const float* __restrict__ jp)
{
    int idx = blockIdx.x * 256 + threadIdx.x;
    bool bad = false;
    if (idx < II * OO * PP) {
        bad = (zp[idx] != zp[idx & 15]);
    } else {
        int r = idx - II * OO * PP;
        if      (r < 65536)  bad = (lp[r]          != lp[0]);
        else if (r < 131072) bad = (sp[r - 65536]  != sp[0]);
        else if (r < 196608) bad = (jp[r - 131072] != jp[0]);
    }
    if (bad) g_fast = 0;
}

// ============================ fast path =====================================
// per (n,i): f = c2*Qi*e rows of Et, varpart via e.f
__global__ void __launch_bounds__(128) k_nx(const float* __restrict__ xm,
                                            const float* __restrict__ xv)
{
    if (!g_fast) return;
    __shared__ float Qi[256], z[16], zz[16], scs[3];
    int t = threadIdx.x;            // n
    int i = blockIdx.x;
    Qi[t]       = g_Qi[t];
    Qi[t + 128] = g_Qi[t + 128];
    if (t < 16) { z[t] = g_z[t]; zz[t] = g_zz[t]; }
    if (t < 3) scs[t] = g_sc[t];
    __syncthreads();
    float l2 = scs[0], A = scs[1], t4 = scs[2];

    float xmv = xm[t * II + i];
    float xvv = xv[t * II + i];
    float v  = xvv + l2;
    float rs = rsqrtf(v);
    float c1 = KLOG * rs * rs;
    float c2 = C2G * rs;
    float a0 = c1 * xmv * xmv;
    float a1 = -2.0f * c1 * xmv;

    float e[16];
#pragma unroll
    for (int p = 0; p < 16; p++) {
        float tt = fmaf(a1, z[p], a0);
        tt = fmaf(c1, zz[p], tt);
        e[p] = ex2(tt);
    }

    float ef = 0.0f;
#pragma unroll
    for (int p = 0; p < 16; p++) {
        float f = Qi[p * 16] * e[0];
#pragma unroll
        for (int q = 1; q < 16; q++) f = fmaf(Qi[p * 16 + q], e[q], f);
        g_Et[(size_t)(i * 16 + p) * NN + t] = c2 * f;
        ef = fmaf(e[p], f, ef);
    }

    float rr = rsqrtf(fmaf(2.0f, xvv, l2));
    g_vp[i * NN + t] = fmaf(A, rr, -t4 * (c2 * c2) * ef);
}

// split-K GEMM: part[kc][n][o] = sum_{k in chunk} Et[k][n] * h[i][o][p], k=i*16+p
__global__ void __launch_bounds__(256) k_gemm(const float* __restrict__ h)
{
    if (!g_fast) return;
    __shared__ float sE[32 * 132];
    __shared__ float sW[32 * 36];
    const int tid = threadIdx.x;
    const int ot = blockIdx.x;      // 0..7
    const int kc = blockIdx.y;      // 0..15
    const int obase = ot * 32;
    const int tx = tid & 7, ty = tid >> 3;
    const int o0 = tx * 4, n0 = ty * 4;

    // h-load decomposition: tid -> (di, oo, j)
    const int hj  = tid & 3;
    const int hoo = (tid >> 2) & 31;
    const int hdi = tid >> 7;

    u64 acc[2][4] = {{0,0,0,0},{0,0,0,0}};

    for (int ks = 0; ks < 8; ks++) {
        const int kk = kc * 256 + ks * 32;
        const int i0 = kk >> 4;
#pragma unroll
        for (int j = 0; j < 4; j++) {
            int c = tid + j * 256;
            int k = c >> 5, nn = (c & 31) * 4;
            float4 v = *(const float4*)&g_Et[(size_t)(kk + k) * NN + nn];
            *(float4*)&sE[k * 132 + nn] = v;
        }
        {
            float4 v = *(const float4*)&h[((size_t)(i0 + hdi) * OO + obase + hoo) * 16 + 4 * hj];
            int kl = hdi * 16 + 4 * hj;
            sW[(kl + 0) * 36 + hoo] = v.x;
            sW[(kl + 1) * 36 + hoo] = v.y;
            sW[(kl + 2) * 36 + hoo] = v.z;
            sW[(kl + 3) * 36 + hoo] = v.w;
        }
        __syncthreads();
#pragma unroll
        for (int k = 0; k < 32; k++) {
            float4 ev = *(const float4*)&sE[k * 132 + n0];
            float4 wv = *(const float4*)&sW[k * 36 + o0];
            u64 e01 = pk2(ev.x, ev.y);
            u64 e23 = pk2(ev.z, ev.w);
            u64 w0 = pk2(wv.x, wv.x), w1 = pk2(wv.y, wv.y);
            u64 w2 = pk2(wv.z, wv.z), w3 = pk2(wv.w, wv.w);
            acc[0][0] = ffma2(e01, w0, acc[0][0]);
            acc[0][1] = ffma2(e01, w1, acc[0][1]);
            acc[0][2] = ffma2(e01, w2, acc[0][2]);
            acc[0][3] = ffma2(e01, w3, acc[0][3]);
            acc[1][0] = ffma2(e23, w0, acc[1][0]);
            acc[1][1] = ffma2(e23, w1, acc[1][1]);
            acc[1][2] = ffma2(e23, w2, acc[1][2]);
            acc[1][3] = ffma2(e23, w3, acc[1][3]);
        }
        __syncthreads();
    }
    float r[4][4];
#pragma unroll
    for (int a = 0; a < 2; a++)
#pragma unroll
        for (int b = 0; b < 4; b++) upk2(r[2*a][b], r[2*a+1][b], acc[a][b]);
#pragma unroll
    for (int rr = 0; rr < 4; rr++) {
        float4 v = make_float4(r[rr][0], r[rr][1], r[rr][2], r[rr][3]);
        *(float4*)&g_part[(size_t)kc * NN * OO + (n0 + rr) * OO + obase + o0] = v;
    }
}

// final: sum split-K partials + var reduction, write both outputs
__global__ void __launch_bounds__(256) k_final(float* __restrict__ out)
{
    if (!g_fast) return;
    __shared__ float sv[256];
    int n = blockIdx.x, o = threadIdx.x;
    sv[o] = g_vp[o * NN + n];       // o indexes i here
    __syncthreads();
    if (o < 128) sv[o] += sv[o + 128];
    __syncthreads();
    if (o < 64) sv[o] += sv[o + 64];
    __syncthreads();
    if (o < 32) {
        float s = sv[o] + sv[o + 32];
#pragma unroll
        for (int off = 16; off; off >>= 1) s += __shfl_down_sync(0xffffffff, s, off);
        if (o == 0) sv[0] = s;
    }
    __syncthreads();
    float svar = sv[0];
    float m = 0.0f;
#pragma unroll
    for (int kc = 0; kc < 16; kc++) m += g_part[(size_t)kc * NN * OO + n * OO + o];
    out[n * OO + o] = m;
    out[NN * OO + n * OO + o] = svar + 25.6f;   // I * GLOBAL_JITTER
}

// ======================= general path (fallback) ============================
__global__ void __launch_bounds__(128) precompute_kernel(
    const float* __restrict__ xm, const float* __restrict__ xv,
    const float* __restrict__ zp, const float* __restrict__ h,
    const float* __restrict__ lp, const float* __restrict__ sp,
    const float* __restrict__ jp)
{
    if (g_fast) return;
    int idx = blockIdx.x * 128 + threadIdx.x;
    if (idx >= II * OO) return;
    if (idx < NN * II) {
        int n = idx / II, i = idx % II;
        g_xmT[i * NN + n] = xm[idx];
        g_xvT[i * NN + n] = xv[idx];
    }
    float z[PP];
    const float* zrow = zp + idx * PP;
#pragma unroll
    for (int p = 0; p < PP; p++) z[p] = tanhf(zrow[p]);
    float l   = __expf(lp[idx]) + 0.2f;
    float s   = __expf(sp[idx]) + 0.1f;
    float jit = __expf(jp[idx]) + 0.01f;
    float l2  = l * l;
    float coef  = __fdividef(1.0f, l * SQ2PI);
    float c1    = -__fdividef(0.72134752044448170f, l2);
    float noise = jit * jit * coef * __fdividef(1.0f, s * s);
    float L[136];
#pragma unroll
    for (int p = 0; p < PP; p++)
#pragma unroll
        for (int q = 0; q <= p; q++) {
            float d = z[p] - z[q];
            float v = coef * ex2(c1 * d * d);
            if (q == p) v += noise;
            L[TRI(p, q)] = v;
        }
    float invd[PP];
#pragma unroll
    for (int k = 0; k < PP; k++) {
        float akk = L[TRI(k, k)];
        float rs  = rsqrtf(akk);
        invd[k]   = rs;
        L[TRI(k, k)] = akk * rs;
#pragma unroll
        for (int p = k + 1; p < PP; p++) L[TRI(p, k)] *= rs;
#pragma unroll
        for (int p = k + 1; p < PP; p++)
#pragma unroll
            for (int q = k + 1; q <= p; q++)
                L[TRI(p, q)] -= L[TRI(p, k)] * L[TRI(q, k)];
    }
    float y[PP];
    const float* hr = h + idx * PP;
#pragma unroll
    for (int p = 0; p < PP; p++) {
        float acc = hr[p];
#pragma unroll
        for (int q = 0; q < p; q++) acc -= L[TRI(p, q)] * y[q];
        y[p] = acc * invd[p];
    }
    float w[PP];
#pragma unroll
    for (int pi = PP - 1; pi >= 0; pi--) {
        float acc = y[pi];
#pragma unroll
        for (int q = pi + 1; q < PP; q++) acc -= L[TRI(q, pi)] * w[q];
        w[pi] = acc * invd[pi];
    }
#pragma unroll
    for (int q = 0; q < PP; q++) {
        L[TRI(q, q)] = invd[q];
#pragma unroll
        for (int p = q + 1; p < PP; p++) {
            float acc = 0.0f;
#pragma unroll
            for (int r = q; r < p; r++) acc += L[TRI(p, r)] * L[TRI(r, q)];
            L[TRI(p, q)] = -acc * invd[p];
        }
    }
    float* blob = g_blob + (size_t)idx * STRIDE;
    blob[0] = l2;
    blob[1] = s * s * l;
    blob[2] = SQ2PI * s * s * l;
    blob[3] = 0.0f;
    u64* b64 = (u64*)(blob + 4);
#pragma unroll
    for (int p = 0; p < PP; p++) b64[p]      = pk2(z[p], z[p]);
#pragma unroll
    for (int p = 0; p < PP; p++) b64[16 + p] = pk2(z[p] * z[p], z[p] * z[p]);
#pragma unroll
    for (int p = 0; p < PP; p++) b64[32 + p] = pk2(w[p], w[p]);
#pragma unroll
    for (int k = 0; k < 136; k++) b64[48 + k] = pk2(L[k], L[k]);
}

__global__ void __launch_bounds__(512) main_kernel(float* __restrict__ out)
{
    if (g_fast) return;
    const int o = blockIdx.x, t = threadIdx.x;
    const int w = t >> 5, lane = t & 31;
    const int n0 = lane * 4;
    __shared__ float stage[16][STRIDE];
    __shared__ float smM[16][NN];
    __shared__ float smV[16][NN];
    float* buf = stage[w];
    float macc0 = 0.f, macc1 = 0.f, macc2 = 0.f, macc3 = 0.f;
    float vacc0 = 0.f, vacc1 = 0.f, vacc2 = 0.f, vacc3 = 0.f;
    int i = w * 16;
    const size_t step4 = (size_t)OO * (STRIDE / 4);
    const float4* gb = (const float4*)(g_blob + ((size_t)i * OO + o) * STRIDE);
    float4 p0 = gb[lane];
    float4 p1 = gb[lane + 32];
    float4 p2 = make_float4(0.f, 0.f, 0.f, 0.f);
    if (lane < 29) p2 = gb[lane + 64];
#pragma unroll 1
    for (int it = 0; it < 16; ++it, ++i) {
        __syncwarp();
        ((float4*)buf)[lane]      = p0;
        ((float4*)buf)[lane + 32] = p1;
        if (lane < 29) ((float4*)buf)[lane + 64] = p2;
        __syncwarp();
        if (it < 15) {
            gb += step4;
            p0 = gb[lane];
            p1 = gb[lane + 32];
            if (lane < 29) p2 = gb[lane + 64];
        }
        const float l2 = buf[0], A = buf[1], t4 = buf[2];
        const float4 xm4 = *(const float4*)&g_xmT[i * NN + n0];
        const float4 xv4 = *(const float4*)&g_xvT[i * NN + n0];
        float rs0 = rsqrtf(xv4.x + l2), rs1 = rsqrtf(xv4.y + l2);
        float rs2 = rsqrtf(xv4.z + l2), rs3 = rsqrtf(xv4.w + l2);
        float c10 = KLOG * rs0 * rs0, c11 = KLOG * rs1 * rs1;
        float c12 = KLOG * rs2 * rs2, c13 = KLOG * rs3 * rs3;
        float c20 = C2G * rs0, c21 = C2G * rs1, c22 = C2G * rs2, c23 = C2G * rs3;
        float a00 = c10 * xm4.x * xm4.x, a01 = c11 * xm4.y * xm4.y;
        float a02 = c12 * xm4.z * xm4.z, a03 = c13 * xm4.w * xm4.w;
        float a10 = -2.f * c10 * xm4.x, a11 = -2.f * c11 * xm4.y;
        float a12 = -2.f * c12 * xm4.z, a13 = -2.f * c13 * xm4.w;
        u64 c1a = pk2(c10, c11), c1b = pk2(c12, c13);
        u64 a0a = pk2(a00, a01), a0b = pk2(a02, a03);
        u64 a1a = pk2(a10, a11), a1b = pk2(a12, a13);
        const u64* zd  = (const u64*)(buf + 4);
        const u64* z2d = (const u64*)(buf + 36);
        const u64* wd  = (const u64*)(buf + 68);
        const u64* Lid = (const u64*)(buf + 100);
        u64 ea[PP], eb[PP];
#pragma unroll
        for (int p = 0; p < PP; p++) {
            u64 ta = ffma2(a1a, zd[p], a0a);
            ta = ffma2(c1a, z2d[p], ta);
            u64 tb = ffma2(a1b, zd[p], a0b);
            tb = ffma2(c1b, z2d[p], tb);
            float lo, hi;
            upk2(lo, hi, ta); ea[p] = pk2(ex2(lo), ex2(hi));
            upk2(lo, hi, tb); eb[p] = pk2(ex2(lo), ex2(hi));
        }
        u64 da = fmul2(ea[0], wd[0]);
        u64 db = fmul2(eb[0], wd[0]);
#pragma unroll
        for (int p = 1; p < PP; p++) {
            da = ffma2(ea[p], wd[p], da);
            db = ffma2(eb[p], wd[p], db);
        }
        u64 t5a = 0, t5b = 0;
#pragma unroll
        for (int p = 0; p < PP; p++) {
            const int k0 = p * (p + 1) / 2;
            u64 ua = fmul2(Lid[k0], ea[0]);
            u64 ub = fmul2(Lid[k0], eb[0]);
#pragma unroll
            for (int q = 1; q <= p; q++) {
                ua = ffma2(Lid[k0 + q], ea[q], ua);
                ub = ffma2(Lid[k0 + q], eb[q], ub);
            }
            if (p == 0) { t5a = fmul2(ua, ua); t5b = fmul2(ub, ub); }
            else        { t5a = ffma2(ua, ua, t5a); t5b = ffma2(ub, ub, t5b); }
        }
        float d0, d1, d2, d3, s0, s1, s2, s3;
        upk2(d0, d1, da); upk2(d2, d3, db);
        upk2(s0, s1, t5a); upk2(s2, s3, t5b);
        macc0 = fmaf(c20, d0, macc0);
        macc1 = fmaf(c21, d1, macc1);
        macc2 = fmaf(c22, d2, macc2);
        macc3 = fmaf(c23, d3, macc3);
        float rr0 = rsqrtf(fmaf(2.f, xv4.x, l2));
        float rr1 = rsqrtf(fmaf(2.f, xv4.y, l2));
        float rr2 = rsqrtf(fmaf(2.f, xv4.z, l2));
        float rr3 = rsqrtf(fmaf(2.f, xv4.w, l2));
        vacc0 += fmaf(A, rr0, -(t4 * c20 * c20) * s0);
        vacc1 += fmaf(A, rr1, -(t4 * c21 * c21) * s1);
        vacc2 += fmaf(A, rr2, -(t4 * c22 * c22) * s2);
        vacc3 += fmaf(A, rr3, -(t4 * c23 * c23) * s3);
    }
    smM[w][n0] = macc0; smM[w][n0+1] = macc1; smM[w][n0+2] = macc2; smM[w][n0+3] = macc3;
    smV[w][n0] = vacc0; smV[w][n0+1] = vacc1; smV[w][n0+2] = vacc2; smV[w][n0+3] = vacc3;
    __syncthreads();
    if (t < NN) {
        float s = 0.f;
#pragma unroll
        for (int ww = 0; ww < 16; ww++) s += smM[ww][t];
        out[t * OO + o] = s;
    } else if (t < 2 * NN) {
        int n = t - NN;
        float s = 25.6f;
#pragma unroll
        for (int ww = 0; ww < 16; ww++) s += smV[ww][n];
        out[NN * OO + n * OO + o] = s;
    }
}

// ================================ launch ====================================
extern "C" void kernel_launch(void* const* d_in, const int* in_sizes, int n_in,
                              void* d_out, int out_size)
{
    const float* x_mean = (const float*)d_in[0];
    const float* x_var  = (const float*)d_in[1];
    const float* z_par  = (const float*)d_in[2];
    const float* h      = (const float*)d_in[3];
    const float* l_par  = (const float*)d_in[4];
    const float* s_par  = (const float*)d_in[5];
    const float* j_par  = (const float*)d_in[6];
    float* out = (float*)d_out;

    const int check_elems = II * OO * PP + 3 * II * OO;
    k_setup<<<1, 32>>>(z_par, l_par, s_par, j_par);
    k_check<<<(check_elems + 255) / 256, 256>>>(z_par, l_par, s_par, j_par);
    // fast path (no-ops if non-uniform)
    k_nx<<<II, 128>>>(x_mean, x_var);
    k_gemm<<<dim3(8, 16), 256>>>(h);
    k_final<<<NN, 256>>>(out);
    // general fallback (no-ops if uniform)
    precompute_kernel<<<(II * OO + 127) / 128, 128>>>(x_mean, x_var, z_par, h,
                                                      l_par, s_par, j_par);
    main_kernel<<<OO, 512>>>(out);
}

// round 5
// speedup vs baseline: 1.3677x; 1.3677x over previous
#include <cuda_runtime.h>
#include <cuda_bf16.h>

#define PP 16
#define NN 128
#define II 256
#define OO 256
#define KE 4096          // GEMM inner dim = I*P
#define SPLITK 64
#define TRI(p,q) ((p)*((p)+1)/2 + (q))
#define STRIDE 372       // general-path blob stride

typedef unsigned long long u64;

// ---------------- scratch (static __device__, allocation-free) --------------
__device__ int   g_fast;
__device__ float g_z[16], g_zz[16], g_Qi[256], g_sc[4]; // sc: l2, A, t4
__device__ float g_Et[KE * NN];             // 2 MB : f[k][n], k=i*16+p (c2*Qi*e)
__device__ float g_W [KE * OO];             // 4 MB : h transposed to [k][o]
__device__ float g_part[SPLITK * NN * OO];  // 8 MB : split-K partials
__device__ float g_vp[II * NN];             // varpart[i][n]
// general-path scratch
__device__ float g_blob[(size_t)II * OO * STRIDE];
__device__ float g_xmT[II * NN];
__device__ float g_xvT[II * NN];

__device__ __forceinline__ float ex2(float x) {
    float y; asm("ex2.approx.ftz.f32 %0, %1;" : "=f"(y) : "f"(x)); return y;
}
__device__ __forceinline__ u64 pk2(float lo, float hi) {
    u64 r; asm("mov.b64 %0, {%1,%2};" : "=l"(r) : "f"(lo), "f"(hi)); return r;
}
__device__ __forceinline__ void upk2(float& lo, float& hi, u64 v) {
    asm("mov.b64 {%0,%1}, %2;" : "=f"(lo), "=f"(hi) : "l"(v));
}
__device__ __forceinline__ u64 ffma2(u64 a, u64 b, u64 c) {
    u64 r; asm("fma.rn.f32x2 %0, %1, %2, %3;" : "=l"(r) : "l"(a), "l"(b), "l"(c)); return r;
}
__device__ __forceinline__ u64 fmul2(u64 a, u64 b) {
    u64 r; asm("mul.rn.f32x2 %0, %1, %2;" : "=l"(r) : "l"(a), "l"(b)); return r;
}

#define KLOG (-0.72134752044448170f)   // -log2(e)/2
#define C2G  ( 0.39894228040143270f)   // 1/sqrt(2pi)
#define SQ2PI 2.5066282746310002f

// ============ setup: g_fast=1 + shared 16x16 factorization ==================
__global__ void k_setup(const float* __restrict__ zp, const float* __restrict__ lp,
                        const float* __restrict__ sp, const float* __restrict__ jp)
{
    __shared__ float L[16][16], M[16][16], invd[16], z[16], sc[8];
    int t = threadIdx.x;   // 32 threads
    if (t == 0) g_fast = 1;
    if (t < 16) z[t] = tanhf(zp[t]);
    if (t == 0) {
        float l   = __expf(lp[0]) + 0.2f;
        float s   = __expf(sp[0]) + 0.1f;
        float jit = __expf(jp[0]) + 0.01f;
        float l2  = l * l;
        sc[0] = l2;
        sc[1] = s * s * l;            // A
        sc[2] = SQ2PI * s * s * l;    // t4
        sc[3] = __fdividef(1.0f, l * SQ2PI);              // coef
        sc[4] = -__fdividef(0.72134752044448170f, l2);    // c1z (log2 domain)
        sc[5] = jit * jit * sc[3] * __fdividef(1.0f, s * s); // noise
    }
    __syncwarp();
    if (t < 16) {
        for (int q = 0; q <= t; q++) {
            float d = z[t] - z[q];
            float v = sc[3] * ex2(sc[4] * d * d);
            if (q == t) v += sc[5];
            L[t][q] = v;
        }
    }
    __syncwarp();
    // Cholesky
    for (int k = 0; k < 16; k++) {
        if (t == k) { float rs = rsqrtf(L[k][k]); invd[k] = rs; L[k][k] *= rs; }
        __syncwarp();
        if (t < 16 && t > k) L[t][k] *= invd[k];
        __syncwarp();
        if (t < 16 && t > k)
            for (int q = k + 1; q <= t; q++) L[t][q] -= L[t][k] * L[q][k];
        __syncwarp();
    }
    // Linv column t
    if (t < 16) {
        for (int p = 0; p < t; p++) M[p][t] = 0.0f;
        M[t][t] = invd[t];
        for (int p = t + 1; p < 16; p++) {
            float acc = 0.0f;
            for (int r = t; r < p; r++) acc += L[p][r] * M[r][t];
            M[p][t] = -acc * invd[p];
        }
    }
    __syncwarp();
    // Qinv row t
    if (t < 16) {
        for (int b = 0; b < 16; b++) {
            float s = 0.0f;
            for (int p = 0; p < 16; p++) s += M[p][t] * M[p][b];
            g_Qi[t * 16 + b] = s;
        }
        g_z[t]  = z[t];
        g_zz[t] = z[t] * z[t];
        if (t < 3) g_sc[t] = sc[t];
    }
}

// ============================ uniformity check ==============================
__global__ void __launch_bounds__(256) k_check(
    const float* __restrict__ zp, const float* __restrict__ lp,
    const float* __restrict__ sp, const float* __restrict__ jp)
{
    int idx = blockIdx.x * 256 + threadIdx.x;
    bool bad = false;
    if (idx < II * OO * PP) {
        bad = (zp[idx] != zp[idx & 15]);
    } else {
        int r = idx - II * OO * PP;
        if      (r < 65536)  bad = (lp[r]          != lp[0]);
        else if (r < 131072) bad = (sp[r - 65536]  != sp[0]);
        else if (r < 196608) bad = (jp[r - 131072] != jp[0]);
    }
    if (bad) g_fast = 0;
}

// ============================ fast path =====================================
// per block i: (a) transpose h[i,:,:] -> g_W[k][o]  (all 256 threads)
//              (b) f = c2*Qi*e rows of Et + varpart (threads 0..127, t = n)
__global__ void __launch_bounds__(256) k_nx(const float* __restrict__ xm,
                                            const float* __restrict__ xv,
                                            const float* __restrict__ h)
{
    if (!g_fast) return;
    __shared__ float Qi[256], z[16], zz[16], scs[3];
    int t = threadIdx.x;
    int i = blockIdx.x;
    Qi[t] = g_Qi[t];
    if (t < 16) { z[t] = g_z[t]; zz[t] = g_zz[t]; }
    if (t < 3) scs[t] = g_sc[t];
    __syncthreads();

    // ---- h transpose: warp w handles o = w*32 + lane
    {
        int w = t >> 5, lane = t & 31;
        int o = w * 32 + lane;
        float4 hv[4];
        const float4* hr = (const float4*)(h + ((size_t)i * OO + o) * 16);
#pragma unroll
        for (int j = 0; j < 4; j++) hv[j] = hr[j];
        const float* hf = (const float*)hv;
#pragma unroll
        for (int p = 0; p < 16; p++)
            g_W[(size_t)(i * 16 + p) * OO + o] = hf[p];
    }

    if (t >= 128) return;
    float l2 = scs[0], A = scs[1], t4 = scs[2];

    float xmv = xm[t * II + i];
    float xvv = xv[t * II + i];
    float v  = xvv + l2;
    float rs = rsqrtf(v);
    float c1 = KLOG * rs * rs;
    float c2 = C2G * rs;
    float a0 = c1 * xmv * xmv;
    float a1 = -2.0f * c1 * xmv;

    float e[16];
#pragma unroll
    for (int p = 0; p < 16; p++) {
        float tt = fmaf(a1, z[p], a0);
        tt = fmaf(c1, zz[p], tt);
        e[p] = ex2(tt);
    }

    float ef = 0.0f;
#pragma unroll
    for (int p = 0; p < 16; p++) {
        float f = Qi[p * 16] * e[0];
#pragma unroll
        for (int q = 1; q < 16; q++) f = fmaf(Qi[p * 16 + q], e[q], f);
        g_Et[(size_t)(i * 16 + p) * NN + t] = c2 * f;
        ef = fmaf(e[p], f, ef);
    }

    float rr = rsqrtf(fmaf(2.0f, xvv, l2));
    g_vp[i * NN + t] = fmaf(A, rr, -t4 * (c2 * c2) * ef);
}

// split-K GEMM: 128n x 128o tile, 8x8 per thread, f32x2 accumulators.
// grid (2 o-tiles, 64 k-chunks); kchunk = 64 in four 16-k smem sub-steps.
__global__ void __launch_bounds__(256) k_gemm()
{
    if (!g_fast) return;
    __shared__ float sE[16][132];
    __shared__ float sW[16][132];
    const int tid = threadIdx.x;
    const int obase = blockIdx.x * 128;
    const int kc = blockIdx.y;          // 0..63
    const int tx = tid & 15, ty = tid >> 4;
    const int o0 = tx * 8, n0 = ty * 8;

    u64 acc[8][4];
#pragma unroll
    for (int j = 0; j < 8; j++)
#pragma unroll
        for (int r = 0; r < 4; r++) acc[j][r] = 0;

    const int kk = kc * 64;
#pragma unroll 1
    for (int ss = 0; ss < 4; ss++) {
        const int kkk = kk + ss * 16;
#pragma unroll
        for (int j = 0; j < 2; j++) {
            int idx = tid + j * 256;
            int k = idx >> 5, c = (idx & 31) * 4;
            *(float4*)&sE[k][c] = *(const float4*)&g_Et[(size_t)(kkk + k) * NN + c];
            *(float4*)&sW[k][c] = *(const float4*)&g_W[(size_t)(kkk + k) * OO + obase + c];
        }
        __syncthreads();
#pragma unroll
        for (int k = 0; k < 16; k++) {
            float4 e0 = *(const float4*)&sE[k][n0];
            float4 e1 = *(const float4*)&sE[k][n0 + 4];
            float4 w0 = *(const float4*)&sW[k][o0];
            float4 w1 = *(const float4*)&sW[k][o0 + 4];
            u64 ep[4];
            ep[0] = pk2(e0.x, e0.y); ep[1] = pk2(e0.z, e0.w);
            ep[2] = pk2(e1.x, e1.y); ep[3] = pk2(e1.z, e1.w);
            float wf[8] = {w0.x, w0.y, w0.z, w0.w, w1.x, w1.y, w1.z, w1.w};
#pragma unroll
            for (int j = 0; j < 8; j++) {
                u64 wd = pk2(wf[j], wf[j]);
#pragma unroll
                for (int r = 0; r < 4; r++) acc[j][r] = ffma2(ep[r], wd, acc[j][r]);
            }
        }
        __syncthreads();
    }

    // epilogue: write 8 rows x 8 cols
#pragma unroll
    for (int r = 0; r < 8; r++) {
        float row[8];
#pragma unroll
        for (int j = 0; j < 8; j++) {
            float lo, hi;
            upk2(lo, hi, acc[j][r >> 1]);
            row[j] = (r & 1) ? hi : lo;
        }
        float* dst = &g_part[((size_t)kc * NN + n0 + r) * OO + obase + o0];
        *(float4*)dst       = make_float4(row[0], row[1], row[2], row[3]);
        *(float4*)(dst + 4) = make_float4(row[4], row[5], row[6], row[7]);
    }
}

// final: sum split-K partials + var reduction, write both outputs
__global__ void __launch_bounds__(256) k_final(float* __restrict__ out)
{
    if (!g_fast) return;
    __shared__ float sv[256];
    int n = blockIdx.x, o = threadIdx.x;
    sv[o] = g_vp[o * NN + n];       // o indexes i here
    __syncthreads();
    if (o < 128) sv[o] += sv[o + 128];
    __syncthreads();
    if (o < 64) sv[o] += sv[o + 64];
    __syncthreads();
    if (o < 32) {
        float s = sv[o] + sv[o + 32];
#pragma unroll
        for (int off = 16; off; off >>= 1) s += __shfl_down_sync(0xffffffff, s, off);
        if (o == 0) sv[0] = s;
    }
    __syncthreads();
    float svar = sv[0];
    float m = 0.0f;
#pragma unroll
    for (int kc = 0; kc < SPLITK; kc++)
        m += g_part[((size_t)kc * NN + n) * OO + o];
    out[n * OO + o] = m;
    out[NN * OO + n * OO + o] = svar + 25.6f;   // I * GLOBAL_JITTER
}

// ======================= general path (fallback) ============================
__global__ void __launch_bounds__(128) precompute_kernel(
    const float* __restrict__ xm, const float* __restrict__ xv,
    const float* __restrict__ zp, const float* __restrict__ h,
    const float* __restrict__ lp, const float* __restrict__ sp,
    const float* __restrict__ jp)
{
    if (g_fast) return;
    int idx = blockIdx.x * 128 + threadIdx.x;
    if (idx >= II * OO) return;
    if (idx < NN * II) {
        int n = idx / II, i = idx % II;
        g_xmT[i * NN + n] = xm[idx];
        g_xvT[i * NN + n] = xv[idx];
    }
    float z[PP];
    const float* zrow = zp + idx * PP;
#pragma unroll
    for (int p = 0; p < PP; p++) z[p] = tanhf(zrow[p]);
    float l   = __expf(lp[idx]) + 0.2f;
    float s   = __expf(sp[idx]) + 0.1f;
    float jit = __expf(jp[idx]) + 0.01f;
    float l2  = l * l;
    float coef  = __fdividef(1.0f, l * SQ2PI);
    float c1    = -__fdividef(0.72134752044448170f, l2);
    float noise = jit * jit * coef * __fdividef(1.0f, s * s);
    float L[136];
#pragma unroll
    for (int p = 0; p < PP; p++)
#pragma unroll
        for (int q = 0; q <= p; q++) {
            float d = z[p] - z[q];
            float v = coef * ex2(c1 * d * d);
            if (q == p) v += noise;
            L[TRI(p, q)] = v;
        }
    float invd[PP];
#pragma unroll
    for (int k = 0; k < PP; k++) {
        float akk = L[TRI(k, k)];
        float rs  = rsqrtf(akk);
        invd[k]   = rs;
        L[TRI(k, k)] = akk * rs;
#pragma unroll
        for (int p = k + 1; p < PP; p++) L[TRI(p, k)] *= rs;
#pragma unroll
        for (int p = k + 1; p < PP; p++)
#pragma unroll
            for (int q = k + 1; q <= p; q++)
                L[TRI(p, q)] -= L[TRI(p, k)] * L[TRI(q, k)];
    }
    float y[PP];
    const float* hr = h + idx * PP;
#pragma unroll
    for (int p = 0; p < PP; p++) {
        float acc = hr[p];
#pragma unroll
        for (int q = 0; q < p; q++) acc -= L[TRI(p, q)] * y[q];
        y[p] = acc * invd[p];
    }
    float w[PP];
#pragma unroll
    for (int pi = PP - 1; pi >= 0; pi--) {
        float acc = y[pi];
#pragma unroll
        for (int q = pi + 1; q < PP; q++) acc -= L[TRI(q, pi)] * w[q];
        w[pi] = acc * invd[pi];
    }
#pragma unroll
    for (int q = 0; q < PP; q++) {
        L[TRI(q, q)] = invd[q];
#pragma unroll
        for (int p = q + 1; p < PP; p++) {
            float acc = 0.0f;
#pragma unroll
            for (int r = q; r < p; r++) acc += L[TRI(p, r)] * L[TRI(r, q)];
            L[TRI(p, q)] = -acc * invd[p];
        }
    }
    float* blob = g_blob + (size_t)idx * STRIDE;
    blob[0] = l2;
    blob[1] = s * s * l;
    blob[2] = SQ2PI * s * s * l;
    blob[3] = 0.0f;
    u64* b64 = (u64*)(blob + 4);
#pragma unroll
    for (int p = 0; p < PP; p++) b64[p]      = pk2(z[p], z[p]);
#pragma unroll
    for (int p = 0; p < PP; p++) b64[16 + p] = pk2(z[p] * z[p], z[p] * z[p]);
#pragma unroll
    for (int p = 0; p < PP; p++) b64[32 + p] = pk2(w[p], w[p]);
#pragma unroll
    for (int k = 0; k < 136; k++) b64[48 + k] = pk2(L[k], L[k]);
}

__global__ void __launch_bounds__(512) main_kernel(float* __restrict__ out)
{
    if (g_fast) return;
    const int o = blockIdx.x, t = threadIdx.x;
    const int w = t >> 5, lane = t & 31;
    const int n0 = lane * 4;
    __shared__ float stage[16][STRIDE];
    __shared__ float smM[16][NN];
    __shared__ float smV[16][NN];
    float* buf = stage[w];
    float macc0 = 0.f, macc1 = 0.f, macc2 = 0.f, macc3 = 0.f;
    float vacc0 = 0.f, vacc1 = 0.f, vacc2 = 0.f, vacc3 = 0.f;
    int i = w * 16;
    const size_t step4 = (size_t)OO * (STRIDE / 4);
    const float4* gb = (const float4*)(g_blob + ((size_t)i * OO + o) * STRIDE);
    float4 p0 = gb[lane];
    float4 p1 = gb[lane + 32];
    float4 p2 = make_float4(0.f, 0.f, 0.f, 0.f);
    if (lane < 29) p2 = gb[lane + 64];
#pragma unroll 1
    for (int it = 0; it < 16; ++it, ++i) {
        __syncwarp();
        ((float4*)buf)[lane]      = p0;
        ((float4*)buf)[lane + 32] = p1;
        if (lane < 29) ((float4*)buf)[lane + 64] = p2;
        __syncwarp();
        if (it < 15) {
            gb += step4;
            p0 = gb[lane];
            p1 = gb[lane + 32];
            if (lane < 29) p2 = gb[lane + 64];
        }
        const float l2 = buf[0], A = buf[1], t4 = buf[2];
        const float4 xm4 = *(const float4*)&g_xmT[i * NN + n0];
        const float4 xv4 = *(const float4*)&g_xvT[i * NN + n0];
        float rs0 = rsqrtf(xv4.x + l2), rs1 = rsqrtf(xv4.y + l2);
        float rs2 = rsqrtf(xv4.z + l2), rs3 = rsqrtf(xv4.w + l2);
        float c10 = KLOG * rs0 * rs0, c11 = KLOG * rs1 * rs1;
        float c12 = KLOG * rs2 * rs2, c13 = KLOG * rs3 * rs3;
        float c20 = C2G * rs0, c21 = C2G * rs1, c22 = C2G * rs2, c23 = C2G * rs3;
        float a00 = c10 * xm4.x * xm4.x, a01 = c11 * xm4.y * xm4.y;
        float a02 = c12 * xm4.z * xm4.z, a03 = c13 * xm4.w * xm4.w;
        float a10 = -2.f * c10 * xm4.x, a11 = -2.f * c11 * xm4.y;
        float a12 = -2.f * c12 * xm4.z, a13 = -2.f * c13 * xm4.w;
        u64 c1a = pk2(c10, c11), c1b = pk2(c12, c13);
        u64 a0a = pk2(a00, a01), a0b = pk2(a02, a03);
        u64 a1a = pk2(a10, a11), a1b = pk2(a12, a13);
        const u64* zd  = (const u64*)(buf + 4);
        const u64* z2d = (const u64*)(buf + 36);
        const u64* wd  = (const u64*)(buf + 68);
        const u64* Lid = (const u64*)(buf + 100);
        u64 ea[PP], eb[PP];
#pragma unroll
        for (int p = 0; p < PP; p++) {
            u64 ta = ffma2(a1a, zd[p], a0a);
            ta = ffma2(c1a, z2d[p], ta);
            u64 tb = ffma2(a1b, zd[p], a0b);
            tb = ffma2(c1b, z2d[p], tb);
            float lo, hi;
            upk2(lo, hi, ta); ea[p] = pk2(ex2(lo), ex2(hi));
            upk2(lo, hi, tb); eb[p] = pk2(ex2(lo), ex2(hi));
        }
        u64 da = fmul2(ea[0], wd[0]);
        u64 db = fmul2(eb[0], wd[0]);
#pragma unroll
        for (int p = 1; p < PP; p++) {
            da = ffma2(ea[p], wd[p], da);
            db = ffma2(eb[p], wd[p], db);
        }
        u64 t5a = 0, t5b = 0;
#pragma unroll
        for (int p = 0; p < PP; p++) {
            const int k0 = p * (p + 1) / 2;
            u64 ua = fmul2(Lid[k0], ea[0]);
            u64 ub = fmul2(Lid[k0], eb[0]);
#pragma unroll
            for (int q = 1; q <= p; q++) {
                ua = ffma2(Lid[k0 + q], ea[q], ua);
                ub = ffma2(Lid[k0 + q], eb[q], ub);
            }
            if (p == 0) { t5a = fmul2(ua, ua); t5b = fmul2(ub, ub); }
            else        { t5a = ffma2(ua, ua, t5a); t5b = ffma2(ub, ub, t5b); }
        }
        float d0, d1, d2, d3, s0, s1, s2, s3;
        upk2(d0, d1, da); upk2(d2, d3, db);
        upk2(s0, s1, t5a); upk2(s2, s3, t5b);
        macc0 = fmaf(c20, d0, macc0);
        macc1 = fmaf(c21, d1, macc1);
        macc2 = fmaf(c22, d2, macc2);
        macc3 = fmaf(c23, d3, macc3);
        float rr0 = rsqrtf(fmaf(2.f, xv4.x, l2));
        float rr1 = rsqrtf(fmaf(2.f, xv4.y, l2));
        float rr2 = rsqrtf(fmaf(2.f, xv4.z, l2));
        float rr3 = rsqrtf(fmaf(2.f, xv4.w, l2));
        vacc0 += fmaf(A, rr0, -(t4 * c20 * c20) * s0);
        vacc1 += fmaf(A, rr1, -(t4 * c21 * c21) * s1);
        vacc2 += fmaf(A, rr2, -(t4 * c22 * c22) * s2);
        vacc3 += fmaf(A, rr3, -(t4 * c23 * c23) * s3);
    }
    smM[w][n0] = macc0; smM[w][n0+1] = macc1; smM[w][n0+2] = macc2; smM[w][n0+3] = macc3;
    smV[w][n0] = vacc0; smV[w][n0+1] = vacc1; smV[w][n0+2] = vacc2; smV[w][n0+3] = vacc3;
    __syncthreads();
    if (t < NN) {
        float s = 0.f;
#pragma unroll
        for (int ww = 0; ww < 16; ww++) s += smM[ww][t];
        out[t * OO + o] = s;
    } else if (t < 2 * NN) {
        int n = t - NN;
        float s = 25.6f;
#pragma unroll
        for (int ww = 0; ww < 16; ww++) s += smV[ww][n];
        out[NN * OO + n * OO + o] = s;
    }
}

// ================================ launch ====================================
extern "C" void kernel_launch(void* const* d_in, const int* in_sizes, int n_in,
                              void* d_out, int out_size)
{
    const float* x_mean = (const float*)d_in[0];
    const float* x_var  = (const float*)d_in[1];
    const float* z_par  = (const float*)d_in[2];
    const float* h      = (const float*)d_in[3];
    const float* l_par  = (const float*)d_in[4];
    const float* s_par  = (const float*)d_in[5];
    const float* j_par  = (const float*)d_in[6];
    float* out = (float*)d_out;

    const int check_elems = II * OO * PP + 3 * II * OO;
    k_setup<<<1, 32>>>(z_par, l_par, s_par, j_par);
    k_check<<<(check_elems + 255) / 256, 256>>>(z_par, l_par, s_par, j_par);
    // fast path (no-ops if non-uniform)
    k_nx<<<II, 256>>>(x_mean, x_var, h);
    k_gemm<<<dim3(2, SPLITK), 256>>>();
    k_final<<<NN, 256>>>(out);
    // general fallback (no-ops if uniform)
    precompute_kernel<<<(II * OO + 127) / 128, 128>>>(x_mean, x_var, z_par, h,
                                                      l_par, s_par, j_par);
    main_kernel<<<OO, 512>>>(out);
}